// round 13
// baseline (speedup 1.0000x reference)
#include <cuda_runtime.h>
#include <math.h>

#define D 64
#define C 128
#define H 512
#define BATCH 4096
#define TM 16
#define NTHREADS 512
#define HS 516   // h1T row stride: 516 mod 32 = 4

typedef unsigned long long u64;

__device__ __forceinline__ u64 pack2(float lo, float hi) {
    u64 r; asm("mov.b64 %0, {%1, %2};" : "=l"(r) : "f"(lo), "f"(hi)); return r;
}
__device__ __forceinline__ void fma2(u64& acc, u64 a, u64 b) {
    asm("fma.rn.f32x2 %0, %1, %2, %0;" : "+l"(acc) : "l"(a), "l"(b));
}
__device__ __forceinline__ void unpack2(float& lo, float& hi, u64 v) {
    asm("mov.b64 {%0, %1}, %2;" : "=f"(lo), "=f"(hi) : "l"(v));
}
__device__ __forceinline__ void cp16(unsigned sa, const void* ga) {
    asm volatile("cp.async.cg.shared.global [%0], [%1], 16;" :: "r"(sa), "l"(ga));
}

// Permuted + masked weights (built by prep kernel each launch; idempotent).
__device__ float g_W1p[(D + C) * H];   // [in][p]
__device__ float g_W2pT[H * H];        // [p][j]  transposed masked W2
__device__ float g_W3T[H * 2 * D];     // [p][2*i + {0(mean),1(prescale)}], masked
__device__ float g_b1p[H];
__device__ float g_b2p[H];

// Hidden degrees: m_h[k] = (k % 63) + 1, sorted ascending (ties by k).
__device__ __forceinline__ int permk(int p) {
    if (p < 72) { int d = p / 9; int t = p - 9 * d; return d + 63 * t; }
    int q = p - 72; int d8 = q >> 3; int t = q & 7; return 8 + d8 + 63 * t;
}
__device__ __forceinline__ int degp(int p) {
    return (p < 72) ? (p / 9 + 1) : ((p - 72) / 8 + 9);
}
__device__ __forceinline__ int cntd(int d) {
    return (d <= 0) ? 0 : (d <= 8 ? 9 * d : 8 * d + 8);
}

__global__ void prep_kernel(const float* __restrict__ W1, const float* __restrict__ b1,
                            const float* __restrict__ W2, const float* __restrict__ b2,
                            const float* __restrict__ W3) {
    const int NA = (D + C) * H;
    const int NB = H * H;
    const int NW3 = H * 2 * D;
    const int total = NA + NB + NW3 + 2 * H;
    for (int idx = blockIdx.x * blockDim.x + threadIdx.x; idx < total;
         idx += gridDim.x * blockDim.x) {
        if (idx < NA) {
            int in = idx >> 9, p = idx & 511;
            float m = (in < D) ? ((degp(p) >= in + 1) ? 1.f : 0.f) : 1.f;
            g_W1p[idx] = W1[in * H + permk(p)] * m;
        } else if (idx < NA + NB) {
            int t = idx - NA;
            int p = t >> 9, j = t & 511;
            g_W2pT[t] = (degp(p) >= degp(j)) ? W2[permk(j) * H + permk(p)] : 0.f;
        } else if (idx < NA + NB + NW3) {
            int t = idx - NA - NB;
            int p = t >> 7, q = t & 127;
            int i = q >> 1, hi = q & 1;
            bool m = (degp(p) <= i);
            g_W3T[t] = m ? W3[permk(p) * (2 * D) + hi * D + i] : 0.f;
        } else {
            int t = idx - NA - NB - NW3;
            if (t < H) g_b1p[t] = b1[permk(t)];
            else       g_b2p[t - H] = b2[permk(t - H)];
        }
    }
}

// Column dot product over j range [s,e), with inline h1 update for j >= n2.
__device__ __forceinline__ float dot_col(
    const float* __restrict__ h1row, const float* __restrict__ wrow,
    const float* __restrict__ w1cur, int s, int e, int n2, float zr) {
    u64 a0 = 0, a1 = 0, a2 = 0, a3 = 0;
    const int pe0 = n2 & ~7;
    const int pe = pe0 < e ? pe0 : e;
    int j = s;
    for (; j < pe; j += 8) {
        ulonglong2 hA = *(const ulonglong2*)&h1row[j];
        ulonglong2 hB = *(const ulonglong2*)&h1row[j + 4];
        ulonglong2 wA = *(const ulonglong2*)&wrow[j];
        ulonglong2 wB = *(const ulonglong2*)&wrow[j + 4];
        fma2(a0, hA.x, wA.x); fma2(a1, hA.y, wA.y);
        fma2(a2, hB.x, wB.x); fma2(a3, hB.y, wB.y);
    }
    for (; j < e; j += 8) {       // tail blocks: rows deg==i+1 updated inline
        float hv[8];
#pragma unroll
        for (int k = 0; k < 8; ++k) {
            float x = h1row[j + k];
            if (j + k >= n2) x = fmaxf(x + zr * w1cur[j + k], 0.f);
            hv[k] = x;
        }
        ulonglong2 wA = *(const ulonglong2*)&wrow[j];
        ulonglong2 wB = *(const ulonglong2*)&wrow[j + 4];
        fma2(a0, pack2(hv[0], hv[1]), wA.x);
        fma2(a1, pack2(hv[2], hv[3]), wA.y);
        fma2(a2, pack2(hv[4], hv[5]), wB.x);
        fma2(a3, pack2(hv[6], hv[7]), wB.y);
    }
    float l0, u0, l1, u1, l2, u2, l3, u3;
    unpack2(l0, u0, a0); unpack2(l1, u1, a1);
    unpack2(l2, u2, a2); unpack2(l3, u3, a3);
    return ((l0 + u0) + (l1 + u1)) + ((l2 + u2) + (l3 + u3));
}

// SMEM layout (floats)
#define OF_ACC   (TM * HS)
#define OF_W2    (OF_ACC + D * TM * 2)
#define OF_W3    (OF_W2 + 2 * 4096)
#define OF_W1    (OF_W3 + 2 * 1152)
#define OF_B2    (OF_W1 + 2 * 512)
#define OF_EPS   (OF_B2 + H)
#define OF_B3    (OF_EPS + D * TM)
#define OF_PDOT  (OF_B3 + 2 * D)
#define OF_ZSH   (OF_PDOT + 144 * 4)
#define SMEM_FLOATS (OF_ZSH + TM)
#define SMEM_BYTES (SMEM_FLOATS * 4)

__global__ __launch_bounds__(NTHREADS, 2)
void made_main(const float* __restrict__ qc, const float* __restrict__ eps,
               const float* __restrict__ b3g, float* __restrict__ out) {
    extern __shared__ float sm[];
    float* h1T   = sm;
    float2* accS2 = (float2*)(sm + OF_ACC);
    float* w2sb  = sm + OF_W2;
    float* ctx   = w2sb;                  // overlay, init only
    float* w3sb  = sm + OF_W3;
    float* w1sb  = sm + OF_W1;
    float* b2s   = sm + OF_B2;
    float* epsT  = sm + OF_EPS;
    float* b3s   = sm + OF_B3;
    float* pdot  = sm + OF_PDOT;          // [c][r][4 quarters]
    float* zsh   = sm + OF_ZSH;

    const int tid  = threadIdx.x;
    const int r0   = blockIdx.x * TM;
    const int warp = tid >> 5, lane = tid & 31;
    const int r    = tid & 15;

    const unsigned sa = (unsigned)__cvta_generic_to_shared(sm);
    const unsigned sa_w2 = sa + OF_W2 * 4;
    const unsigned sa_w3 = sa + OF_W3 * 4;
    const unsigned sa_w1 = sa + OF_W1 * 4;

    // ---- prologue staging ----
    for (int u = tid; u < TM * C; u += NTHREADS) {
        int rr = u >> 7, c = u & 127;
        ctx[c * TM + rr] = qc[(r0 + rr) * C + c];
    }
    for (int u = tid; u < D * TM; u += NTHREADS) {
        int i0 = u >> 4, rr = u & 15;
        epsT[i0 * TM + rr] = eps[(r0 + rr) * D + i0];
    }
    for (int u = tid; u < 2 * D; u += NTHREADS) b3s[u] = b3g[u];
    for (int u = tid; u < H; u += NTHREADS) b2s[u] = __ldg(&g_b2p[u]);
    {
        float2* a2 = accS2;
        for (int u = tid; u < D * TM; u += NTHREADS) a2[u] = make_float2(0.f, 0.f);
    }
    __syncthreads();

    // ---- h1_pre init: thread owns hidden unit p, all 16 rows in regs ----
    for (int p = tid; p < H; p += NTHREADS) {
        float acc[TM];
        float b = __ldg(&g_b1p[p]);
#pragma unroll
        for (int rr = 0; rr < TM; ++rr) acc[rr] = b;
        for (int c = 0; c < C; ++c) {
            float w = __ldg(&g_W1p[(D + c) * H + p]);
            float4 x0 = *(const float4*)&ctx[c * TM + 0];
            float4 x1 = *(const float4*)&ctx[c * TM + 4];
            float4 x2 = *(const float4*)&ctx[c * TM + 8];
            float4 x3 = *(const float4*)&ctx[c * TM + 12];
            acc[0]  += x0.x * w; acc[1]  += x0.y * w; acc[2]  += x0.z * w; acc[3]  += x0.w * w;
            acc[4]  += x1.x * w; acc[5]  += x1.y * w; acc[6]  += x1.z * w; acc[7]  += x1.w * w;
            acc[8]  += x2.x * w; acc[9]  += x2.y * w; acc[10] += x2.z * w; acc[11] += x2.w * w;
            acc[12] += x3.x * w; acc[13] += x3.y * w; acc[14] += x3.z * w; acc[15] += x3.w * w;
        }
#pragma unroll
        for (int rr = 0; rr < TM; ++rr) h1T[rr * HS + p] = acc[rr];
    }
    __syncthreads();   // ctx overlay dead; prefetch may overwrite it now

    // ---- prologue prefetch for step 0 (buffers [0]) ----
    {
        const int finn = cntd(1);               // 9
        const int jl32n = (finn + 31) & ~31;    // 32
        if (tid < 128) cp16(sa_w1 + tid * 16, g_W1p + tid * 4);
        const int upr = jl32n >> 2;
        for (int u = tid; u < finn * upr; u += NTHREADS) {
            int c = u / upr, jo = (u - c * upr) << 2;
            cp16(sa_w2 + ((c * jl32n + jo) << 2), g_W2pT + (size_t)c * H + jo);
        }
        for (int u = tid; u < finn * 32; u += NTHREADS)
            cp16(sa_w3 + u * 16, g_W3T + u * 4);
        asm volatile("cp.async.commit_group;");
        asm volatile("cp.async.wait_group 0;");
    }

    // ---- 64 autoregressive steps ----
    for (int i = 0; i < D; ++i) {
        __syncthreads();   // prev scatter/h1/pdot consumed; prefetched bufs visible
        const int n2   = cntd(i);
        const int fin  = cntd(i + 1);
        const int ncol = fin - n2;                // 9 (i<=7) or 8
        const int jl32 = (fin + 31) & ~31;
        const int jq   = jl32 >> 2;               // per-quarter, multiple of 8
        const int cur  = i & 1, nxt = cur ^ 1;
        const float* w1cur = w1sb + cur * 512;
        const float* w2cur = w2sb + cur * 4096;
        const float2* w3cur2 = (const float2*)(w3sb + cur * 1152);

        // ---- z from accumulated projections (computed by every thread) ----
        float2 av = accS2[i * TM + r];
        float mean = av.x + b3s[i];
        float pres = av.y + b3s[D + i];
        float sp = fmaxf(pres, 0.f) + log1pf(expf(-fabsf(pres)));
        float zr = mean + sp * epsT[i * TM + r];
        if (tid < TM) { out[(r0 + tid) * D + i] = zr; zsh[tid] = zr; }

        if (i < D - 1) {
            // ---- prefetch step i+1 resources into [nxt] ----
            if (i + 1 < D - 1) {
                const int n2n = fin;
                const int finn = cntd(i + 2);
                const int ncoln = finn - n2n;
                const int jl32n = (finn + 31) & ~31;
                if (tid < 128)
                    cp16(sa_w1 + nxt * 2048 + tid * 16, g_W1p + (i + 1) * H + tid * 4);
                const int upr = jl32n >> 2;
                for (int u = tid; u < ncoln * upr; u += NTHREADS) {
                    int c = u / upr, jo = (u - c * upr) << 2;
                    cp16(sa_w2 + nxt * 16384 + ((c * jl32n + jo) << 2),
                         g_W2pT + (size_t)(n2n + c) * H + jo);
                }
                for (int u = tid; u < ncoln * 32; u += NTHREADS)
                    cp16(sa_w3 + nxt * 4608 + u * 16, g_W3T + n2n * 128 + u * 4);
            }
            asm volatile("cp.async.commit_group;");

            // ---- dot: 16 warps = 4 col-pairs x 4 j-quarters ----
            {
                const int q = warp >> 2;
                const int s = q * jq, e = s + jq;
                const int c = ((warp & 3) << 1) + (lane >> 4);
                float sum = dot_col(h1T + r * HS, w2cur + c * jl32,
                                    w1cur, s, e, n2, zr);
                pdot[(((c << 4) + r) << 2) + q] = sum;
                if (ncol == 9 && (warp & 3) == 0 && lane < 16) {
                    float s8 = dot_col(h1T + r * HS, w2cur + 8 * jl32,
                                       w1cur, s, e, n2, zr);
                    pdot[((128 + r) << 2) + q] = s8;
                }
            }
            __syncthreads();   // pdot complete

            // ---- scatter: accS[i'] += h2_new * W3T, exclusive (r,i') owner ----
            {
                const int ib = tid >> 4;          // 0..31
                float vals[9];
#pragma unroll
                for (int c2 = 0; c2 < 9; ++c2) {
                    if (c2 < ncol) {
                        float4 pv = *(const float4*)&pdot[((c2 << 4) + r) << 2];
                        vals[c2] = fmaxf((pv.x + pv.y) + (pv.z + pv.w)
                                         + b2s[n2 + c2], 0.f);
                    } else vals[c2] = 0.f;
                }
                for (int i2 = i + 1 + ib; i2 < D; i2 += 32) {
                    float2 a = accS2[i2 * TM + r];
                    for (int c2 = 0; c2 < ncol; ++c2) {
                        float2 w3v = w3cur2[c2 * 64 + i2];
                        a.x += vals[c2] * w3v.x;
                        a.y += vals[c2] * w3v.y;
                    }
                    accS2[i2 * TM + r] = a;
                }
            }

            // ---- deferred rank-1 h1 update: rows [n2, H), relu rows < fin ----
            {
                const int nB = (H - n2) * TM;
                for (int u = tid; u < nB; u += NTHREADS) {
                    int p = n2 + (u >> 4), r2 = u & 15;
                    float v = h1T[r2 * HS + p] + zsh[r2] * w1cur[p];
                    if (p < fin) v = fmaxf(v, 0.f);
                    h1T[r2 * HS + p] = v;
                }
            }
            asm volatile("cp.async.wait_group 0;");   // next-step buffers landed
        }
    }
}

extern "C" void kernel_launch(void* const* d_in, const int* in_sizes, int n_in,
                              void* d_out, int out_size) {
    const float* q   = (const float*)d_in[0];  // (4096, 128)
    const float* eps = (const float*)d_in[1];  // (4096, 64)
    const float* W1  = (const float*)d_in[2];  // (192, 512)
    const float* b1  = (const float*)d_in[3];  // (512,)
    const float* W2  = (const float*)d_in[4];  // (512, 512)
    const float* b2  = (const float*)d_in[5];  // (512,)
    const float* W3  = (const float*)d_in[6];  // (512, 128)
    const float* b3  = (const float*)d_in[7];  // (128,)
    float* out = (float*)d_out;                // (4096, 64)

    cudaFuncSetAttribute(made_main, cudaFuncAttributeMaxDynamicSharedMemorySize,
                         SMEM_BYTES);

    prep_kernel<<<408, 256>>>(W1, b1, W2, b2, W3);
    made_main<<<BATCH / TM, NTHREADS, SMEM_BYTES>>>(q, eps, b3, out);
}

// round 14
// speedup vs baseline: 1.3343x; 1.3343x over previous
#include <cuda_runtime.h>
#include <math.h>

#define D 64
#define C 128
#define H 512
#define BATCH 4096
#define TM 16
#define NTHREADS 256
#define HS 518          // h1T row stride: conflict-free f32x2 reads
#define STAGE_FLOATS 4096

typedef unsigned long long u64;

__device__ __forceinline__ u64 pack2(float lo, float hi) {
    u64 r; asm("mov.b64 %0, {%1, %2};" : "=l"(r) : "f"(lo), "f"(hi)); return r;
}
__device__ __forceinline__ void fma2(u64& acc, u64 a, u64 b) {
    asm("fma.rn.f32x2 %0, %1, %2, %0;" : "+l"(acc) : "l"(a), "l"(b));
}
__device__ __forceinline__ void unpack2(float& lo, float& hi, u64 v) {
    asm("mov.b64 {%0, %1}, %2;" : "=f"(lo), "=f"(hi) : "l"(v));
}
__device__ __forceinline__ void cp16(unsigned sa, const void* ga) {
    asm volatile("cp.async.cg.shared.global [%0], [%1], 16;" :: "r"(sa), "l"(ga));
}

// Permuted + masked weights (built by prep kernel each launch; idempotent).
__device__ float g_W1p[(D + C) * H];   // [in][p]  in-major, masked, hidden perm
__device__ float g_W2pT[H * H];        // [p][j]   TRANSPOSED masked W2 (j = reduction)
__device__ float g_W3pp[D * H * 2];    // [i][p][2] (mean col i, prescale col D+i), masked
__device__ float g_b1p[H];
__device__ float g_b2p[H];

// Hidden degrees: m_h[k] = (k % 63) + 1. Sorted by degree ascending (ties by k).
__device__ __forceinline__ int permk(int p) {
    if (p < 72) { int d = p / 9; int t = p - 9 * d; return d + 63 * t; }
    int q = p - 72; int d8 = q >> 3; int t = q & 7; return 8 + d8 + 63 * t;
}
__device__ __forceinline__ int degp(int p) {
    return (p < 72) ? (p / 9 + 1) : ((p - 72) / 8 + 9);
}
__device__ __forceinline__ int cntd(int d) {
    return (d <= 0) ? 0 : (d <= 8 ? 9 * d : 8 * d + 8);
}

__global__ void prep_kernel(const float* __restrict__ W1, const float* __restrict__ b1,
                            const float* __restrict__ W2, const float* __restrict__ b2,
                            const float* __restrict__ W3) {
    const int NA = (D + C) * H;
    const int NB = H * H;
    const int NC = D * H;
    const int total = NA + NB + NC + 2 * H;
    for (int idx = blockIdx.x * blockDim.x + threadIdx.x; idx < total;
         idx += gridDim.x * blockDim.x) {
        if (idx < NA) {
            int in = idx >> 9, p = idx & 511;
            float m = (in < D) ? ((degp(p) >= in + 1) ? 1.f : 0.f) : 1.f;
            g_W1p[idx] = W1[in * H + permk(p)] * m;
        } else if (idx < NA + NB) {
            int t = idx - NA;
            int p = t >> 9, j = t & 511;     // TRANSPOSED: [p][j]
            g_W2pT[t] = (degp(p) >= degp(j)) ? W2[permk(j) * H + permk(p)] : 0.f;
        } else if (idx < NA + NB + NC) {
            int t = idx - NA - NB;
            int i = t >> 9, p = t & 511;
            int k = permk(p);
            bool m = (degp(p) <= i);   // m_out = i+1 > deg  <=>  deg <= i
            g_W3pp[t * 2 + 0] = m ? W3[k * (2 * D) + i] : 0.f;
            g_W3pp[t * 2 + 1] = m ? W3[k * (2 * D) + D + i] : 0.f;
        } else {
            int t = idx - NA - NB - NC;
            if (t < H) g_b1p[t] = b1[permk(t)];
            else       g_b2p[t - H] = b2[permk(t - H)];
        }
    }
}

// Dynamic smem layout (floats):
//   h1T[TM][HS]     8288   h1, row-contiguous j
//   h2s[H][TM]      8192   cached relu'd h2 cols (ctx overlay during init)
//   stage[4096]            cp.async W2pT tile for this step
//   w3sb[2][1024]   2048   cp.async W3pp row, double-buffered (step parity)
//   w1s[H]           512   cp.async W1p row i
//   epss[TM][D]     1024
//   b3s[2D]          128
//   red[32]           32
#define OF_H2    (TM * HS)
#define OF_STAGE (OF_H2 + H * TM)
#define OF_W3SB  (OF_STAGE + STAGE_FLOATS)
#define OF_W1S   (OF_W3SB + 2048)
#define OF_EPS   (OF_W1S + H)
#define OF_B3    (OF_EPS + TM * D)
#define OF_RED   (OF_B3 + 2 * D)
#define SMEM_FLOATS (OF_RED + 32)
#define SMEM_BYTES (SMEM_FLOATS * 4)

__global__ __launch_bounds__(NTHREADS, 2)
void made_main(const float* __restrict__ qc, const float* __restrict__ eps,
               const float* __restrict__ b3g, float* __restrict__ out) {
    extern __shared__ float sm[];
    float* h1T   = sm;                     // [16][518]
    float* h2s   = sm + OF_H2;             // [512][16]
    float* ctx   = h2s;                    // overlay, init only: [128][16]
    float* stage = sm + OF_STAGE;          // [4096]
    float* w3sb  = sm + OF_W3SB;           // [2][1024]
    float* w1s   = sm + OF_W1S;            // [512]
    float* epss  = sm + OF_EPS;            // [16][64]
    float* b3s   = sm + OF_B3;             // [128]
    float* red   = sm + OF_RED;            // [32]

    const int tid  = threadIdx.x;
    const int r0   = blockIdx.x * TM;
    const int warp = tid >> 5, lane = tid & 31;

    const unsigned stage_sa = (unsigned)__cvta_generic_to_shared(stage);
    const unsigned w3_sa    = (unsigned)__cvta_generic_to_shared(w3sb);
    const unsigned w1_sa    = (unsigned)__cvta_generic_to_shared(w1s);

    // ---- stage ctx (transposed [c][r]), eps rows, b3; zero red ----
    for (int idx = tid; idx < TM * C; idx += NTHREADS) {
        int r = idx >> 7, c = idx & 127;
        ctx[c * TM + r] = qc[(r0 + r) * C + c];
    }
    for (int idx = tid; idx < TM * D; idx += NTHREADS)
        epss[idx] = eps[r0 * D + idx];           // contiguous rows
    for (int idx = tid; idx < 2 * D; idx += NTHREADS)
        b3s[idx] = b3g[idx];
    if (tid < 32) red[tid] = 0.f;
    __syncthreads();

    // ---- h1_pre init: thread owns hidden unit p, all 16 rows in regs ----
    for (int p = tid; p < H; p += NTHREADS) {
        float acc[TM];
        float b = __ldg(&g_b1p[p]);
#pragma unroll
        for (int r = 0; r < TM; ++r) acc[r] = b;
        for (int c = 0; c < C; ++c) {
            float w = __ldg(&g_W1p[(D + c) * H + p]);
            float4 x0 = *(const float4*)&ctx[c * TM + 0];
            float4 x1 = *(const float4*)&ctx[c * TM + 4];
            float4 x2 = *(const float4*)&ctx[c * TM + 8];
            float4 x3 = *(const float4*)&ctx[c * TM + 12];
            acc[0]  += x0.x * w; acc[1]  += x0.y * w; acc[2]  += x0.z * w; acc[3]  += x0.w * w;
            acc[4]  += x1.x * w; acc[5]  += x1.y * w; acc[6]  += x1.z * w; acc[7]  += x1.w * w;
            acc[8]  += x2.x * w; acc[9]  += x2.y * w; acc[10] += x2.z * w; acc[11] += x2.w * w;
            acc[12] += x3.x * w; acc[13] += x3.y * w; acc[14] += x3.z * w; acc[15] += x3.w * w;
        }
#pragma unroll
        for (int r = 0; r < TM; ++r) h1T[r * HS + p] = acc[r];
    }

    // ---- 64 autoregressive steps ----
    for (int i = 0; i < D; ++i) {
        __syncthreads();   // h2s/stage/w3sb from prev step; red reset visible
        const int n2   = cntd(i);
        const int fin  = cntd(i + 1);
        const int ncol = fin - n2;                 // 8 or 9
        const int jlim = (fin + 7) & ~7;           // pad rows masked-zero in W2pT

        // ---- prefetch: group 0 = W1p row i + W3pp row i+1 (next step) ----
        if (tid < 128)
            cp16(w1_sa + tid * 16, g_W1p + i * H + tid * 4);
        if (i + 1 < D) {
            const int nu = (cntd(i + 1) + 1) >> 1;   // 16B units of 2*fin floats
            const unsigned dst = w3_sa + (((i + 1) & 1) << 12);
            for (int u = tid; u < nu; u += NTHREADS)
                cp16(dst + u * 16, g_W3pp + (size_t)(i + 1) * 1024 + u * 4);
        }
        asm volatile("cp.async.commit_group;");
        // ---- group 1 = W2pT tile for THIS step's Phase C ----
        if (i < D - 1) {
            const int nunit = (ncol * jlim) >> 2;  // 16B units
            const int upr = jlim >> 2;             // units per row
            for (int u = tid; u < nunit; u += NTHREADS) {
                int c = u / upr, jo = (u - c * upr) << 2;
                cp16(stage_sa + ((c * jlim + jo) << 2),
                     g_W2pT + (size_t)(n2 + c) * H + jo);
            }
        }
        asm volatile("cp.async.commit_group;");

        // ---- Phase A: projection over cached h2 prefix, W3 from SMEM ----
        {
            const float2* w3cur = (const float2*)(w3sb + ((i & 1) << 10));
            const int pl = tid >> 4, r = tid & 15;
            float mmv = 0.f, ppv = 0.f;
            for (int p = pl; p < n2; p += 16) {
                float hv = h2s[p * TM + r];
                float2 w3 = w3cur[p];
                mmv += hv * w3.x; ppv += hv * w3.y;
            }
            mmv += __shfl_xor_sync(0xffffffffu, mmv, 16);
            ppv += __shfl_xor_sync(0xffffffffu, ppv, 16);
            if (lane < 16) {
                atomicAdd(&red[lane], mmv);
                atomicAdd(&red[16 + lane], ppv);
            }
        }
        asm volatile("cp.async.wait_group 1;");   // W1 row + next-W3 landed
        __syncthreads();   // red complete + w1s visible to all

        // ---- z for this warp's two rows (computed redundantly per warp) ----
        const int ra = warp * 2, rb = ra + 1;
        float za, zb;
        {
            float mean = red[ra] + b3s[i];
            float pres = red[16 + ra] + b3s[D + i];
            float sp = fmaxf(pres, 0.f) + log1pf(expf(-fabsf(pres)));
            za = mean + sp * epss[ra * D + i];
            mean = red[rb] + b3s[i];
            pres = red[16 + rb] + b3s[D + i];
            sp = fmaxf(pres, 0.f) + log1pf(expf(-fabsf(pres)));
            zb = mean + sp * epss[rb * D + i];
        }
        if (tid < TM) {    // one thread per row writes the output sample
            float mean = red[tid] + b3s[i];
            float pres = red[16 + tid] + b3s[D + i];
            float sp = fmaxf(pres, 0.f) + log1pf(expf(-fabsf(pres)));
            out[(r0 + tid) * D + i] = mean + sp * epss[tid * D + i];
        }

        // ---- Phase B: rank-1 h1 update, suffix rows deg >= i+1 (from w1s) ----
        for (int p = n2 + lane; p < H; p += 32) {
            float wv = w1s[p];
            float va = h1T[ra * HS + p] + za * wv;
            float vb = h1T[rb * HS + p] + zb * wv;
            if (p < fin) { va = fmaxf(va, 0.f); vb = fmaxf(vb, 0.f); }
            h1T[ra * HS + p] = va;
            h1T[rb * HS + p] = vb;
        }
        asm volatile("cp.async.wait_group 0;");   // W2 tile landed (own copies)
        __syncthreads();   // h1 final thru deg i+1 + stage visible to all

        // ---- Phase C: compute NEW h2 columns (deg == i+1) from staged W2 ----
        if (tid < 32) red[tid] = 0.f;   // all red readers passed the barrier
        if (i < D - 1 && tid < ncol * TM) {
            const int c = tid >> 4, rr = tid & 15;
            const int p = n2 + c;
            const float* hrow = h1T + rr * HS;
            const float* wc   = stage + c * jlim;
            u64 a0 = 0, a1 = 0, a2 = 0, a3 = 0;
#pragma unroll 2
            for (int j = 0; j < jlim; j += 8) {
                float2 h0 = *(const float2*)&hrow[j];
                float2 h1v = *(const float2*)&hrow[j + 2];
                float2 h2v = *(const float2*)&hrow[j + 4];
                float2 h3 = *(const float2*)&hrow[j + 6];
                float4 wa = *(const float4*)&wc[j];        // broadcast
                float4 wb = *(const float4*)&wc[j + 4];    // broadcast
                fma2(a0, pack2(h0.x, h0.y), pack2(wa.x, wa.y));
                fma2(a1, pack2(h1v.x, h1v.y), pack2(wa.z, wa.w));
                fma2(a2, pack2(h2v.x, h2v.y), pack2(wb.x, wb.y));
                fma2(a3, pack2(h3.x, h3.y), pack2(wb.z, wb.w));
            }
            float l0, u0, l1, u1, l2, u2, l3, u3;
            unpack2(l0, u0, a0); unpack2(l1, u1, a1);
            unpack2(l2, u2, a2); unpack2(l3, u3, a3);
            float s = __ldg(&g_b2p[p]) + ((l0 + u0) + (l1 + u1))
                                       + ((l2 + u2) + (l3 + u3));
            h2s[p * TM + rr] = fmaxf(s, 0.f);   // store relu'd
        }
        // top-of-loop barrier orders h2s/stage/w3sb before next step
    }
}

extern "C" void kernel_launch(void* const* d_in, const int* in_sizes, int n_in,
                              void* d_out, int out_size) {
    const float* q   = (const float*)d_in[0];  // (4096, 128)
    const float* eps = (const float*)d_in[1];  // (4096, 64)
    const float* W1  = (const float*)d_in[2];  // (192, 512)
    const float* b1  = (const float*)d_in[3];  // (512,)
    const float* W2  = (const float*)d_in[4];  // (512, 512)
    const float* b2  = (const float*)d_in[5];  // (512,)
    const float* W3  = (const float*)d_in[6];  // (512, 128)
    const float* b3  = (const float*)d_in[7];  // (128,)
    float* out = (float*)d_out;                // (4096, 64)

    cudaFuncSetAttribute(made_main, cudaFuncAttributeMaxDynamicSharedMemorySize,
                         SMEM_BYTES);

    prep_kernel<<<408, 256>>>(W1, b1, W2, b2, W3);
    made_main<<<BATCH / TM, NTHREADS, SMEM_BYTES>>>(q, eps, b3, out);
}

// round 15
// speedup vs baseline: 1.3470x; 1.0095x over previous
#include <cuda_runtime.h>
#include <math.h>

#define D 64
#define C 128
#define H 512
#define BATCH 4096
#define TM 16
#define NTHREADS 256
#define HS 518          // h1T row stride: conflict-free f32x2 reads
#define STAGE_FLOATS 4096

typedef unsigned long long u64;

__device__ __forceinline__ u64 pack2(float lo, float hi) {
    u64 r; asm("mov.b64 %0, {%1, %2};" : "=l"(r) : "f"(lo), "f"(hi)); return r;
}
__device__ __forceinline__ void fma2(u64& acc, u64 a, u64 b) {
    asm("fma.rn.f32x2 %0, %1, %2, %0;" : "+l"(acc) : "l"(a), "l"(b));
}
__device__ __forceinline__ void unpack2(float& lo, float& hi, u64 v) {
    asm("mov.b64 {%0, %1}, %2;" : "=f"(lo), "=f"(hi) : "l"(v));
}
__device__ __forceinline__ void cp16(unsigned sa, const void* ga) {
    asm volatile("cp.async.cg.shared.global [%0], [%1], 16;" :: "r"(sa), "l"(ga));
}

// Permuted + masked weights (built by prep kernel each launch; idempotent).
__device__ float g_W1p[(D + C) * H];   // [in][p]  in-major, masked, hidden perm
__device__ float g_W2pT[H * H];        // [p][j]   TRANSPOSED masked W2 (j = reduction)
__device__ float g_W3pp[D * H * 2];    // [i][p][2] (mean col i, prescale col D+i), masked
__device__ float g_b1p[H];
__device__ float g_b2p[H];

// Hidden degrees: m_h[k] = (k % 63) + 1. Sorted by degree ascending (ties by k).
__device__ __forceinline__ int permk(int p) {
    if (p < 72) { int d = p / 9; int t = p - 9 * d; return d + 63 * t; }
    int q = p - 72; int d8 = q >> 3; int t = q & 7; return 8 + d8 + 63 * t;
}
__device__ __forceinline__ int degp(int p) {
    return (p < 72) ? (p / 9 + 1) : ((p - 72) / 8 + 9);
}
__device__ __forceinline__ int cntd(int d) {
    return (d <= 0) ? 0 : (d <= 8 ? 9 * d : 8 * d + 8);
}

__global__ void prep_kernel(const float* __restrict__ W1, const float* __restrict__ b1,
                            const float* __restrict__ W2, const float* __restrict__ b2,
                            const float* __restrict__ W3) {
    const int NA = (D + C) * H;
    const int NB = H * H;
    const int NC = D * H;
    const int total = NA + NB + NC + 2 * H;
    for (int idx = blockIdx.x * blockDim.x + threadIdx.x; idx < total;
         idx += gridDim.x * blockDim.x) {
        if (idx < NA) {
            int in = idx >> 9, p = idx & 511;
            float m = (in < D) ? ((degp(p) >= in + 1) ? 1.f : 0.f) : 1.f;
            g_W1p[idx] = W1[in * H + permk(p)] * m;
        } else if (idx < NA + NB) {
            int t = idx - NA;
            int p = t >> 9, j = t & 511;     // TRANSPOSED: [p][j]
            g_W2pT[t] = (degp(p) >= degp(j)) ? W2[permk(j) * H + permk(p)] : 0.f;
        } else if (idx < NA + NB + NC) {
            int t = idx - NA - NB;
            int i = t >> 9, p = t & 511;
            int k = permk(p);
            bool m = (degp(p) <= i);   // m_out = i+1 > deg  <=>  deg <= i
            g_W3pp[t * 2 + 0] = m ? W3[k * (2 * D) + i] : 0.f;
            g_W3pp[t * 2 + 1] = m ? W3[k * (2 * D) + D + i] : 0.f;
        } else {
            int t = idx - NA - NB - NC;
            if (t < H) g_b1p[t] = b1[permk(t)];
            else       g_b2p[t - H] = b2[permk(t - H)];
        }
    }
}

// Partial dot over j range [s,e) (both multiples of 8).
__device__ __forceinline__ float dot_partial(
    const float* __restrict__ hrow, const float* __restrict__ wrow, int s, int e) {
    u64 a0 = 0, a1 = 0, a2 = 0, a3 = 0;
#pragma unroll 2
    for (int j = s; j < e; j += 8) {
        float2 h0 = *(const float2*)&hrow[j];
        float2 h1v = *(const float2*)&hrow[j + 2];
        float2 h2v = *(const float2*)&hrow[j + 4];
        float2 h3 = *(const float2*)&hrow[j + 6];
        float4 wa = *(const float4*)&wrow[j];
        float4 wb = *(const float4*)&wrow[j + 4];
        fma2(a0, pack2(h0.x, h0.y), pack2(wa.x, wa.y));
        fma2(a1, pack2(h1v.x, h1v.y), pack2(wa.z, wa.w));
        fma2(a2, pack2(h2v.x, h2v.y), pack2(wb.x, wb.y));
        fma2(a3, pack2(h3.x, h3.y), pack2(wb.z, wb.w));
    }
    float l0, u0, l1, u1, l2, u2, l3, u3;
    unpack2(l0, u0, a0); unpack2(l1, u1, a1);
    unpack2(l2, u2, a2); unpack2(l3, u3, a3);
    return ((l0 + u0) + (l1 + u1)) + ((l2 + u2) + (l3 + u3));
}

// Dynamic smem layout (floats):
//   h1T[TM][HS]     8288
//   h2s[H][TM]      8192   (ctx overlay during init)
//   stage[4096]            cp.async W2pT tile
//   w3sb[2][1024]   2048   cp.async W3pp row, double-buffered
//   w1s[H]           512   cp.async W1p row i
//   b2s[H]           512
//   epss[TM][D]     1024
//   b3s[2D]          128
//   red[32]           32
//   pdot[2][9][16]   288   Phase-C half partials (combined next step)
#define OF_H2    (TM * HS)
#define OF_STAGE (OF_H2 + H * TM)
#define OF_W3SB  (OF_STAGE + STAGE_FLOATS)
#define OF_W1S   (OF_W3SB + 2048)
#define OF_B2S   (OF_W1S + H)
#define OF_EPS   (OF_B2S + H)
#define OF_B3    (OF_EPS + TM * D)
#define OF_RED   (OF_B3 + 2 * D)
#define OF_PDOT  (OF_RED + 32)
#define SMEM_FLOATS (OF_PDOT + 288)
#define SMEM_BYTES (SMEM_FLOATS * 4)

__global__ __launch_bounds__(NTHREADS, 2)
void made_main(const float* __restrict__ qc, const float* __restrict__ eps,
               const float* __restrict__ b3g, float* __restrict__ out) {
    extern __shared__ float sm[];
    float* h1T   = sm;                     // [16][518]
    float* h2s   = sm + OF_H2;             // [512][16]
    float* ctx   = h2s;                    // overlay, init only: [128][16]
    float* stage = sm + OF_STAGE;          // [4096]
    float* w3sb  = sm + OF_W3SB;           // [2][1024]
    float* w1s   = sm + OF_W1S;            // [512]
    float* b2s   = sm + OF_B2S;            // [512]
    float* epss  = sm + OF_EPS;            // [16][64]
    float* b3s   = sm + OF_B3;             // [128]
    float* red   = sm + OF_RED;            // [32]
    float* pdot  = sm + OF_PDOT;           // [2][9][16]

    const int tid  = threadIdx.x;
    const int r0   = blockIdx.x * TM;
    const int warp = tid >> 5, lane = tid & 31;

    const unsigned stage_sa = (unsigned)__cvta_generic_to_shared(stage);
    const unsigned w3_sa    = (unsigned)__cvta_generic_to_shared(w3sb);
    const unsigned w1_sa    = (unsigned)__cvta_generic_to_shared(w1s);

    // ---- stage ctx (transposed [c][r]), eps rows, b3, b2; zero red ----
    for (int idx = tid; idx < TM * C; idx += NTHREADS) {
        int r = idx >> 7, c = idx & 127;
        ctx[c * TM + r] = qc[(r0 + r) * C + c];
    }
    for (int idx = tid; idx < TM * D; idx += NTHREADS)
        epss[idx] = eps[r0 * D + idx];           // contiguous rows
    for (int idx = tid; idx < 2 * D; idx += NTHREADS)
        b3s[idx] = b3g[idx];
    for (int idx = tid; idx < H; idx += NTHREADS)
        b2s[idx] = __ldg(&g_b2p[idx]);
    if (tid < 32) red[tid] = 0.f;
    __syncthreads();

    // ---- h1_pre init: thread owns hidden unit p, all 16 rows in regs ----
    for (int p = tid; p < H; p += NTHREADS) {
        float acc[TM];
        float b = __ldg(&g_b1p[p]);
#pragma unroll
        for (int r = 0; r < TM; ++r) acc[r] = b;
        for (int c = 0; c < C; ++c) {
            float w = __ldg(&g_W1p[(D + c) * H + p]);
            float4 x0 = *(const float4*)&ctx[c * TM + 0];
            float4 x1 = *(const float4*)&ctx[c * TM + 4];
            float4 x2 = *(const float4*)&ctx[c * TM + 8];
            float4 x3 = *(const float4*)&ctx[c * TM + 12];
            acc[0]  += x0.x * w; acc[1]  += x0.y * w; acc[2]  += x0.z * w; acc[3]  += x0.w * w;
            acc[4]  += x1.x * w; acc[5]  += x1.y * w; acc[6]  += x1.z * w; acc[7]  += x1.w * w;
            acc[8]  += x2.x * w; acc[9]  += x2.y * w; acc[10] += x2.z * w; acc[11] += x2.w * w;
            acc[12] += x3.x * w; acc[13] += x3.y * w; acc[14] += x3.z * w; acc[15] += x3.w * w;
        }
#pragma unroll
        for (int r = 0; r < TM; ++r) h1T[r * HS + p] = acc[r];
    }

    // ---- 64 autoregressive steps ----
    for (int i = 0; i < D; ++i) {
        __syncthreads();   // prev pdot/h2s/stage/w3sb visible; red reset visible
        const int n2   = cntd(i);
        const int n2p  = (i > 0) ? cntd(i - 1) : 0;    // prev-step prefix
        const int fin  = cntd(i + 1);
        const int ncol = fin - n2;                 // 8 or 9
        const int jlim = (fin + 7) & ~7;           // pad rows masked-zero in W2pT

        // ---- prefetch: group 0 = W1p row i + W3pp row i+1 (next step) ----
        if (tid < 128)
            cp16(w1_sa + tid * 16, g_W1p + i * H + tid * 4);
        if (i + 1 < D) {
            const int nu = (cntd(i + 1) + 1) >> 1;   // 16B units of 2*fin floats
            const unsigned dst = w3_sa + (((i + 1) & 1) << 12);
            for (int u = tid; u < nu; u += NTHREADS)
                cp16(dst + u * 16, g_W3pp + (size_t)(i + 1) * 1024 + u * 4);
        }
        asm volatile("cp.async.commit_group;");
        // ---- group 1 = W2pT tile for THIS step's Phase C ----
        if (i < D - 1) {
            const int nunit = (ncol * jlim) >> 2;  // 16B units
            const int upr = jlim >> 2;             // units per row
            for (int u = tid; u < nunit; u += NTHREADS) {
                int c = u / upr, jo = (u - c * upr) << 2;
                cp16(stage_sa + ((c * jlim + jo) << 2),
                     g_W2pT + (size_t)(n2 + c) * H + jo);
            }
        }
        asm volatile("cp.async.commit_group;");

        // ---- Phase A: projection; combine prev-step pdot on first touch ----
        {
            const float2* w3cur = (const float2*)(w3sb + ((i & 1) << 10));
            const int pl = tid >> 4, r = tid & 15;
            float mmv = 0.f, ppv = 0.f;
            // established columns
            for (int p = pl; p < n2p; p += 16) {
                float hv = h2s[p * TM + r];
                float2 w3 = w3cur[p];
                mmv += hv * w3.x; ppv += hv * w3.y;
            }
            // newly finalized columns: combine halves + b2 + relu, cache
            {
                int p0 = n2p + ((pl - n2p) & 15);
                for (int p = p0; p < n2; p += 16) {
                    int c = p - n2p;
                    float hv = fmaxf(pdot[c * TM + r] + pdot[144 + c * TM + r]
                                     + b2s[p], 0.f);
                    h2s[p * TM + r] = hv;
                    float2 w3 = w3cur[p];
                    mmv += hv * w3.x; ppv += hv * w3.y;
                }
            }
            mmv += __shfl_xor_sync(0xffffffffu, mmv, 16);
            ppv += __shfl_xor_sync(0xffffffffu, ppv, 16);
            if (lane < 16 && n2 > 0) {
                atomicAdd(&red[lane], mmv);
                atomicAdd(&red[16 + lane], ppv);
            }
        }
        asm volatile("cp.async.wait_group 1;");   // W1 row + next-W3 landed
        __syncthreads();   // red complete + w1s visible to all

        // ---- z for this warp's two rows (computed redundantly per warp) ----
        const int ra = warp * 2, rb = ra + 1;
        float za, zb;
        {
            float mean = red[ra] + b3s[i];
            float pres = red[16 + ra] + b3s[D + i];
            float sp = fmaxf(pres, 0.f) + log1pf(expf(-fabsf(pres)));
            za = mean + sp * epss[ra * D + i];
            mean = red[rb] + b3s[i];
            pres = red[16 + rb] + b3s[D + i];
            sp = fmaxf(pres, 0.f) + log1pf(expf(-fabsf(pres)));
            zb = mean + sp * epss[rb * D + i];
        }
        if (tid < TM) {    // one thread per row writes the output sample
            float mean = red[tid] + b3s[i];
            float pres = red[16 + tid] + b3s[D + i];
            float sp = fmaxf(pres, 0.f) + log1pf(expf(-fabsf(pres)));
            out[(r0 + tid) * D + i] = mean + sp * epss[tid * D + i];
        }

        // ---- Phase B: rank-1 h1 update, suffix rows deg >= i+1 (from w1s) ----
        for (int p = n2 + lane; p < H; p += 32) {
            float wv = w1s[p];
            float va = h1T[ra * HS + p] + za * wv;
            float vb = h1T[rb * HS + p] + zb * wv;
            if (p < fin) { va = fmaxf(va, 0.f); vb = fmaxf(vb, 0.f); }
            h1T[ra * HS + p] = va;
            h1T[rb * HS + p] = vb;
        }
        asm volatile("cp.async.wait_group 0;");   // W2 tile landed (own copies)
        __syncthreads();   // h1 final thru deg i+1 + stage visible to all

        // ---- Phase C: half-split partial dots for NEW h2 cols (deg i+1) ----
        if (tid < 32) red[tid] = 0.f;   // all red readers passed the barrier
        if (i < D - 1) {
            const int half = tid >> 7;            // 0,1
            const int c = (tid >> 4) & 7;         // 0..7
            const int rr = tid & 15;
            const int jh0 = ((jlim >> 1) + 7) & ~7;
            const int s = half ? jh0 : 0;
            const int e = half ? jlim : jh0;
            const float* hrow = h1T + rr * HS;
            pdot[half * 144 + c * TM + rr] =
                dot_partial(hrow, stage + c * jlim, s, e);
            if (ncol == 9 && c == 0) {
                pdot[half * 144 + 8 * TM + rr] =
                    dot_partial(hrow, stage + 8 * jlim, s, e);
            }
        }
        // top-of-loop barrier orders pdot/h2s/stage/w3sb before next step
    }
}

extern "C" void kernel_launch(void* const* d_in, const int* in_sizes, int n_in,
                              void* d_out, int out_size) {
    const float* q   = (const float*)d_in[0];  // (4096, 128)
    const float* eps = (const float*)d_in[1];  // (4096, 64)
    const float* W1  = (const float*)d_in[2];  // (192, 512)
    const float* b1  = (const float*)d_in[3];  // (512,)
    const float* W2  = (const float*)d_in[4];  // (512, 512)
    const float* b2  = (const float*)d_in[5];  // (512,)
    const float* W3  = (const float*)d_in[6];  // (512, 128)
    const float* b3  = (const float*)d_in[7];  // (128,)
    float* out = (float*)d_out;                // (4096, 64)

    cudaFuncSetAttribute(made_main, cudaFuncAttributeMaxDynamicSharedMemorySize,
                         SMEM_BYTES);

    prep_kernel<<<408, 256>>>(W1, b1, W2, b2, W3);
    made_main<<<BATCH / TM, NTHREADS, SMEM_BYTES>>>(q, eps, b3, out);
}